// round 2
// baseline (speedup 1.0000x reference)
#include <cuda_runtime.h>
#include <math.h>

#define BATCH 2
#define CDIM  512
#define HEADS 8
#define DHEAD 64
#define NPIX  4096
#define KTOP  32
#define GDIM  128

typedef unsigned long long ull;

#define NEG_INF (__int_as_float(0xff800000))

// ---------------- scratch (device globals; no allocation allowed) ----------------
__device__ float g_q[BATCH*HEADS*DHEAD*NPIX];   // [b][h][d][n]
__device__ float g_k[BATCH*HEADS*DHEAD*NPIX];   // [b][h][d][n]
__device__ float g_v[BATCH*HEADS*NPIX*DHEAD];   // [b][h][n][d]
__device__ float g_g1[BATCH*NPIX*GDIM];         // [b][n][o]  gate hidden (bias applied)
__device__ float g_attn[BATCH*CDIM*NPIX];       // [b][c][n]  attention output (pre-proj)
__device__ int   g_kdyn[BATCH*NPIX];

// ---------------- f32x2 helpers (sm_103a packed fp32) ----------------
__device__ __forceinline__ ull fma2(ull a, ull b, ull c) {
    ull d;
    asm("fma.rn.f32x2 %0, %1, %2, %3;" : "=l"(d) : "l"(a), "l"(b), "l"(c));
    return d;
}
__device__ __forceinline__ ull dup2(float x) {
    ull r; unsigned u = __float_as_uint(x);
    asm("mov.b64 %0, {%1, %1};" : "=l"(r) : "r"(u));
    return r;
}
__device__ __forceinline__ float lo2(ull x) { return __uint_as_float((unsigned)x); }
__device__ __forceinline__ float hi2(ull x) { return __uint_as_float((unsigned)(x >> 32)); }

// =====================================================================
// Kernel 1: fused qkv conv (1536 rows) + gate conv1 (128 rows) GEMM
//   C[o,n] = sum_c W[o,c] * x[b,c,n],  o in [0,1664)
// Scatter: q,k -> [b,h,d,n]; v -> [b,h,n,d]; g1 -> [b,n,o]+bias
// =====================================================================
__global__ void __launch_bounds__(128) k_qkv(const float* __restrict__ x,
                                             const float* __restrict__ w_qkv,
                                             const float* __restrict__ w_g1,
                                             const float* __restrict__ b_g1)
{
    __shared__ __align__(16) float As[16 * 68];
    __shared__ __align__(16) float Bs[16 * 64];
    const int b  = blockIdx.z;
    const int o0 = blockIdx.y * 64;
    const int n0 = blockIdx.x * 64;
    const int t  = threadIdx.x;
    const int to = (t >> 3) * 4;   // 4 output rows per thread
    const int tn = (t & 7) * 8;    // 8 output cols per thread (4 f32x2 pairs)
    const float* xb = x + (size_t)b * CDIM * NPIX;

    ull acc[4][4];
#pragma unroll
    for (int i = 0; i < 4; i++)
#pragma unroll
        for (int p = 0; p < 4; p++) acc[i][p] = 0ULL;

    for (int c0 = 0; c0 < CDIM; c0 += 16) {
        // A tile [64 o x 16 c] -> As[c][o] (pitch 68)
#pragma unroll
        for (int r = 0; r < 2; r++) {
            int e = t + r * 128;            // 0..255 float4 units
            int o_l = e >> 2;
            int c_l = (e & 3) * 4;
            int o = o0 + o_l;
            const float* src = (o < 1536) ? (w_qkv + (size_t)o * CDIM + c0 + c_l)
                                          : (w_g1 + (size_t)(o - 1536) * CDIM + c0 + c_l);
            float4 v4 = *(const float4*)src;
            As[(c_l + 0) * 68 + o_l] = v4.x;
            As[(c_l + 1) * 68 + o_l] = v4.y;
            As[(c_l + 2) * 68 + o_l] = v4.z;
            As[(c_l + 3) * 68 + o_l] = v4.w;
        }
        // B tile [16 c x 64 n]
#pragma unroll
        for (int r = 0; r < 8; r++) {
            int e = t + r * 128;
            int n_l = e & 63, c_l = e >> 6;
            Bs[c_l * 64 + n_l] = xb[(size_t)(c0 + c_l) * NPIX + n0 + n_l];
        }
        __syncthreads();
#pragma unroll
        for (int cc = 0; cc < 16; cc++) {
            ull a[4], bb[4];
#pragma unroll
            for (int i = 0; i < 4; i++) a[i] = dup2(As[cc * 68 + to + i]);
            const ull* bp = (const ull*)(Bs + cc * 64 + tn);
#pragma unroll
            for (int p = 0; p < 4; p++) bb[p] = bp[p];
#pragma unroll
            for (int i = 0; i < 4; i++)
#pragma unroll
                for (int p = 0; p < 4; p++) acc[i][p] = fma2(a[i], bb[p], acc[i][p]);
        }
        __syncthreads();
    }

#pragma unroll
    for (int i = 0; i < 4; i++) {
        int o = o0 + to + i;
#pragma unroll
        for (int p = 0; p < 4; p++) {
            int n = n0 + tn + 2 * p;
            float v0 = lo2(acc[i][p]);
            float v1 = hi2(acc[i][p]);
            if (o < 512) {
                int h = o >> 6, d = o & 63;
                float* dst = g_q + (((size_t)(b * HEADS + h)) * DHEAD + d) * NPIX + n;
                dst[0] = v0; dst[1] = v1;
            } else if (o < 1024) {
                int oo = o - 512; int h = oo >> 6, d = oo & 63;
                float* dst = g_k + (((size_t)(b * HEADS + h)) * DHEAD + d) * NPIX + n;
                dst[0] = v0; dst[1] = v1;
            } else if (o < 1536) {
                int oo = o - 1024; int h = oo >> 6, d = oo & 63;
                float* dst = g_v + (((size_t)(b * HEADS + h)) * NPIX + n) * DHEAD + d;
                dst[0] = v0; dst[DHEAD] = v1;
            } else {
                int oo = o - 1536;
                float bg = b_g1[oo];
                float* dst = g_g1 + ((size_t)b * NPIX + n) * GDIM + oo;
                dst[0] = v0 + bg; dst[GDIM] = v1 + bg;
            }
        }
    }
}

// =====================================================================
// Kernel 2: gate second conv -> sigmoid -> dynamic k. One warp per pixel.
// =====================================================================
__global__ void __launch_bounds__(128) k_gate(const float* __restrict__ w_g2,
                                              const float* __restrict__ b_g2)
{
    int p = blockIdx.x * 4 + (threadIdx.x >> 5);   // pixel (b*NPIX + n)
    int lane = threadIdx.x & 31;
    const float* g = g_g1 + (size_t)p * GDIM;
    float acc = 0.f;
#pragma unroll
    for (int r = 0; r < 4; r++) {
        int o = lane + r * 32;
        float gv = g[o];
        gv = gv > 0.f ? gv : 0.f;
        acc += gv * w_g2[o];
    }
#pragma unroll
    for (int s = 16; s; s >>= 1) acc += __shfl_xor_sync(0xffffffffu, acc, s);
    if (lane == 0) {
        float tau = 1.f / (1.f + expf(-(acc + b_g2[0])));
        int kd = (int)(tau * 32.f);     // truncation matches astype(int32)
        kd = kd < 4 ? 4 : (kd > 32 ? 32 : kd);
        g_kdyn[p] = kd;
    }
}

// =====================================================================
// Kernel 3: fused sim GEMM + streaming top-32 (per-query min-heap) +
//           masked softmax + v gather + coalesced output.
// grid: (NPIX/64 query tiles, B*HEADS), 128 threads.
// =====================================================================
#define SMEM_ATTN 66048

__global__ void __launch_bounds__(128) k_attn()
{
    extern __shared__ __align__(16) float sm[];
    float* qs  = sm;                 // [64 d][64 q]   4096
    float* ks  = qs + 4096;         // [64 d][64 j]   4096
    float* sim = ks + 4096;         // [64 q][65]     4160
    float* hv  = sim + 4160;        // heap vals [32][64]  2048
    int*   hid = (int*)(hv + 2048); // heap idx  [32][64]  2048
    int*   kds = hid + 2048;        // [64]
    // reuses after phases end:
    float* sel_w = qs;              // [64][32]
    int*   sel_i = (int*)ks;        // [64][32]
    float* outs  = sim;             // [64 d][65]

    const int bh = blockIdx.y;
    const int b  = bh >> 3;
    const int h  = bh & 7;
    const int q0 = blockIdx.x * 64;
    const int t  = threadIdx.x;

    const float* qg = g_q + (size_t)bh * DHEAD * NPIX;
    const float* kg = g_k + (size_t)bh * DHEAD * NPIX;
    const float* vg = g_v + (size_t)bh * NPIX * DHEAD;

    // load q tile [64 d][64 q], init heaps, load k_dyn
    for (int e = t; e < 4096; e += 128) {
        int d = e >> 6, i = e & 63;
        qs[e] = qg[(size_t)d * NPIX + q0 + i];
    }
    for (int e = t; e < 2048; e += 128) { hv[e] = NEG_INF; hid[e] = 0; }
    if (t < 64) kds[t] = g_kdyn[b * NPIX + q0 + t];
    __syncthreads();

    const int tq = (t >> 3) * 4;
    const int tj = (t & 7) * 8;

    for (int jt = 0; jt < 64; jt++) {
        // load k tile [64 d][64 j]
        for (int e = t; e < 4096; e += 128) {
            int d = e >> 6, j = e & 63;
            ks[e] = kg[(size_t)d * NPIX + jt * 64 + j];
        }
        __syncthreads();

        // 64x64 sim tile via f32x2
        ull acc[4][4];
#pragma unroll
        for (int i = 0; i < 4; i++)
#pragma unroll
            for (int p = 0; p < 4; p++) acc[i][p] = 0ULL;
#pragma unroll 4
        for (int dd = 0; dd < 64; dd++) {
            ull a[4], bb[4];
#pragma unroll
            for (int i = 0; i < 4; i++) a[i] = dup2(qs[dd * 64 + tq + i]);
            const ull* bp = (const ull*)(ks + dd * 64 + tj);
#pragma unroll
            for (int p = 0; p < 4; p++) bb[p] = bp[p];
#pragma unroll
            for (int i = 0; i < 4; i++)
#pragma unroll
                for (int p = 0; p < 4; p++) acc[i][p] = fma2(a[i], bb[p], acc[i][p]);
        }
#pragma unroll
        for (int i = 0; i < 4; i++)
#pragma unroll
            for (int p = 0; p < 4; p++) {
                sim[(tq + i) * 65 + tj + 2 * p]     = lo2(acc[i][p]) * 0.125f;
                sim[(tq + i) * 65 + tj + 2 * p + 1] = hi2(acc[i][p]) * 0.125f;
            }
        __syncthreads();

        // streaming top-32 update: owner thread per query, min-heap at hv[0..31][q]
        if (t < 64) {
            const int q = t;
            const int jbase = jt * 64;
            float rootv = hv[q];
            for (int j = 0; j < 64; j++) {
                float val = sim[q * 65 + j];
                if (val > rootv) {           // strict: keeps lowest index on ties
                    float cv = val; int ci = jbase + j;
                    int s = 0;
                    while (true) {
                        int l = 2 * s + 1, r = 2 * s + 2;
                        int m = s; float mv = cv;
                        if (l < 32) { float lv = hv[l * 64 + q]; if (lv < mv) { m = l; mv = lv; } }
                        if (r < 32) { float rv = hv[r * 64 + q]; if (rv < mv) { m = r; mv = rv; } }
                        if (m == s) break;
                        hv[s * 64 + q]  = mv;
                        hid[s * 64 + q] = hid[m * 64 + q];
                        s = m;
                    }
                    hv[s * 64 + q] = cv; hid[s * 64 + q] = ci;
                    rootv = hv[q];
                }
            }
        }
        __syncthreads();
    }

    // sort heap descending, apply k_dyn mask + softmax -> sel_w/sel_i
    if (t < 64) {
        const int q = t;
        for (int i = 1; i < 32; i++) {
            float kv = hv[i * 64 + q]; int ki = hid[i * 64 + q];
            int j = i - 1;
            while (j >= 0 && hv[j * 64 + q] < kv) {
                hv[(j + 1) * 64 + q]  = hv[j * 64 + q];
                hid[(j + 1) * 64 + q] = hid[j * 64 + q];
                j--;
            }
            hv[(j + 1) * 64 + q] = kv; hid[(j + 1) * 64 + q] = ki;
        }
        int kd = kds[q];
        float m = hv[q];                     // max
        float sum = 0.f;
        for (int s = 0; s < 32; s++) {
            float e = (s < kd) ? expf(hv[s * 64 + q] - m) : 0.f;
            sel_w[q * 32 + s] = e;
            sum += e;
        }
        float inv = 1.f / sum;
        for (int s = 0; s < 32; s++) {
            sel_w[q * 32 + s] *= inv;
            sel_i[q * 32 + s] = hid[s * 64 + q];
        }
    }
    __syncthreads();

    // weighted v gather: thread -> (q, 32-d half)
    {
        const int q   = t >> 1;
        const int dhh = (t & 1) * 32;
        float acc[32];
#pragma unroll
        for (int u = 0; u < 32; u++) acc[u] = 0.f;
#pragma unroll 4
        for (int s = 0; s < 32; s++) {
            float w  = sel_w[q * 32 + s];
            int  idx = sel_i[q * 32 + s];
            const float4* vr = (const float4*)(vg + (size_t)idx * DHEAD + dhh);
#pragma unroll
            for (int u = 0; u < 8; u++) {
                float4 vv = vr[u];
                acc[u * 4 + 0] += w * vv.x;
                acc[u * 4 + 1] += w * vv.y;
                acc[u * 4 + 2] += w * vv.z;
                acc[u * 4 + 3] += w * vv.w;
            }
        }
#pragma unroll
        for (int u = 0; u < 32; u++)
            outs[(dhh + u) * 65 + q] = acc[u];
    }
    __syncthreads();

    // coalesced write: g_attn[b][h*64+d][q0+q]
    float* ab = g_attn + ((size_t)(b * CDIM + h * DHEAD)) * NPIX + q0;
    for (int e = t; e < 4096; e += 128) {
        int d = e >> 6, qq = e & 63;
        ab[(size_t)d * NPIX + qq] = outs[d * 65 + qq];
    }
}

// =====================================================================
// Kernel 4: proj conv + bias + residual
//   out[b,c,n] = x[b,c,n] + b_proj[c] + sum_cc w_proj[c,cc]*g_attn[b,cc,n]
// =====================================================================
__global__ void __launch_bounds__(128) k_proj(const float* __restrict__ x,
                                              const float* __restrict__ w_proj,
                                              const float* __restrict__ b_proj,
                                              float* __restrict__ out)
{
    __shared__ __align__(16) float As[16 * 68];
    __shared__ __align__(16) float Bs[16 * 64];
    const int b  = blockIdx.z;
    const int o0 = blockIdx.y * 64;
    const int n0 = blockIdx.x * 64;
    const int t  = threadIdx.x;
    const int to = (t >> 3) * 4;
    const int tn = (t & 7) * 8;
    const float* ab = g_attn + (size_t)b * CDIM * NPIX;

    ull acc[4][4];
#pragma unroll
    for (int i = 0; i < 4; i++)
#pragma unroll
        for (int p = 0; p < 4; p++) acc[i][p] = 0ULL;

    for (int c0 = 0; c0 < CDIM; c0 += 16) {
#pragma unroll
        for (int r = 0; r < 2; r++) {
            int e = t + r * 128;
            int o_l = e >> 2;
            int c_l = (e & 3) * 4;
            float4 v4 = *(const float4*)(w_proj + (size_t)(o0 + o_l) * CDIM + c0 + c_l);
            As[(c_l + 0) * 68 + o_l] = v4.x;
            As[(c_l + 1) * 68 + o_l] = v4.y;
            As[(c_l + 2) * 68 + o_l] = v4.z;
            As[(c_l + 3) * 68 + o_l] = v4.w;
        }
#pragma unroll
        for (int r = 0; r < 8; r++) {
            int e = t + r * 128;
            int n_l = e & 63, c_l = e >> 6;
            Bs[c_l * 64 + n_l] = ab[(size_t)(c0 + c_l) * NPIX + n0 + n_l];
        }
        __syncthreads();
#pragma unroll
        for (int cc = 0; cc < 16; cc++) {
            ull a[4], bb[4];
#pragma unroll
            for (int i = 0; i < 4; i++) a[i] = dup2(As[cc * 68 + to + i]);
            const ull* bp = (const ull*)(Bs + cc * 64 + tn);
#pragma unroll
            for (int p = 0; p < 4; p++) bb[p] = bp[p];
#pragma unroll
            for (int i = 0; i < 4; i++)
#pragma unroll
                for (int p = 0; p < 4; p++) acc[i][p] = fma2(a[i], bb[p], acc[i][p]);
        }
        __syncthreads();
    }

#pragma unroll
    for (int i = 0; i < 4; i++) {
        int o = o0 + to + i;
        float bp0 = b_proj[o];
#pragma unroll
        for (int p = 0; p < 4; p++) {
            int n = n0 + tn + 2 * p;
            size_t base = ((size_t)b * CDIM + o) * NPIX + n;
            out[base]     = lo2(acc[i][p]) + bp0 + x[base];
            out[base + 1] = hi2(acc[i][p]) + bp0 + x[base + 1];
        }
    }
}

// =====================================================================
extern "C" void kernel_launch(void* const* d_in, const int* in_sizes, int n_in,
                              void* d_out, int out_size)
{
    const float* x      = (const float*)d_in[0];
    const float* w_qkv  = (const float*)d_in[1];
    const float* w_proj = (const float*)d_in[2];
    const float* b_proj = (const float*)d_in[3];
    const float* w_g1   = (const float*)d_in[4];
    const float* b_g1   = (const float*)d_in[5];
    const float* w_g2   = (const float*)d_in[6];
    const float* b_g2   = (const float*)d_in[7];
    float* out = (float*)d_out;

    cudaFuncSetAttribute(k_attn, cudaFuncAttributeMaxDynamicSharedMemorySize, SMEM_ATTN);

    k_qkv<<<dim3(NPIX / 64, 26, BATCH), 128>>>(x, w_qkv, w_g1, b_g1);
    k_gate<<<(BATCH * NPIX) / 4, 128>>>(w_g2, b_g2);
    k_attn<<<dim3(NPIX / 64, BATCH * HEADS), 128, SMEM_ATTN>>>();
    k_proj<<<dim3(NPIX / 64, CDIM / 64, BATCH), 128>>>(x, w_proj, b_proj, out);
}